// round 2
// baseline (speedup 1.0000x reference)
#include <cuda_runtime.h>

#define N_NODES 50000
#define D_IN    256
#define D_HID   512
#define N_EDGES 800000

// Scratch (static device globals: allocation-free per harness rules)
__device__ float g_agg[(size_t)N_NODES * D_IN];   // 51.2 MB neighbor-sum
__device__ float g_cnt[N_NODES];                  // in-degree
__device__ int   g_is64;                          // edge_index dtype flag

// ---------------------------------------------------------------------------
// Detect whether edge_index is int64 or int32. Values are in [0, 50000), so
// if stored as int64 every odd 32-bit word (hi half) is 0. With int32, those
// words are random indices — P(all 128 == 0) ~ 0. Deterministic.
// ---------------------------------------------------------------------------
__global__ void detect_kernel(const unsigned int* __restrict__ e) {
    if (threadIdx.x == 0) {
        int is64 = 1;
        for (int i = 0; i < 128; i++)
            if (e[2 * i + 1] != 0u) { is64 = 0; break; }
        g_is64 = is64;
    }
}

__global__ void zero_kernel() {
    int idx = blockIdx.x * blockDim.x + threadIdx.x;
    int stride = gridDim.x * blockDim.x;
    float4 z = make_float4(0.f, 0.f, 0.f, 0.f);
    float4* a4 = reinterpret_cast<float4*>(g_agg);
    const int n4 = N_NODES * D_IN / 4;
    for (int i = idx; i < n4; i += stride) a4[i] = z;
    for (int i = idx; i < N_NODES; i += stride) g_cnt[i] = 0.f;
}

// ---------------------------------------------------------------------------
// Scatter: one warp per edge. 64 float4 loads of x[src] (L2-resident),
// 256 scalar atomicAdd (-> RED.E.ADD.F32, no return) into g_agg[dst].
// ---------------------------------------------------------------------------
__global__ __launch_bounds__(256) void scatter_kernel(
    const float* __restrict__ x, const void* __restrict__ eidx)
{
    int gw   = (blockIdx.x * blockDim.x + threadIdx.x) >> 5;
    int lane = threadIdx.x & 31;
    if (gw >= N_EDGES) return;

    int src, dst;
    if (g_is64) {
        const long long* p = (const long long*)eidx;
        src = (int)p[gw];
        dst = (int)p[N_EDGES + gw];
    } else {
        const int* p = (const int*)eidx;
        src = p[gw];
        dst = p[N_EDGES + gw];
    }

    const float4* xs = (const float4*)(x + (size_t)src * D_IN);
    float* ad = g_agg + (size_t)dst * D_IN;

#pragma unroll
    for (int i = 0; i < 2; i++) {
        int c = lane + 32 * i;          // float4 index 0..63
        float4 v = xs[c];
        atomicAdd(ad + 4 * c + 0, v.x);
        atomicAdd(ad + 4 * c + 1, v.y);
        atomicAdd(ad + 4 * c + 2, v.z);
        atomicAdd(ad + 4 * c + 3, v.w);
    }
    if (lane == 0) atomicAdd(&g_cnt[dst], 1.0f);
}

// ---------------------------------------------------------------------------
// Fused GEMM: out = (agg * inv_cnt) @ W_l + x @ W_r + b
// 64x64 output tile, BK=16, 256 threads, 4x4 per-thread microtile.
// Mean division folded into the A1 shared-memory store.
// ---------------------------------------------------------------------------
#define BM 64
#define BN 64
#define BK 16

__global__ __launch_bounds__(256) void gemm_kernel(
    const float* __restrict__ x,  const float* __restrict__ Wl,
    const float* __restrict__ Wr, const float* __restrict__ bias,
    float* __restrict__ out)
{
    __shared__ float sA1[BK][BM];
    __shared__ float sA2[BK][BM];
    __shared__ float sB1[BK][BN];
    __shared__ float sB2[BK][BN];
    __shared__ float sInv[BM];

    const int tid  = threadIdx.x;
    const int row0 = blockIdx.x * BM;
    const int col0 = blockIdx.y * BN;

    if (tid < BM) {
        int r = row0 + tid;
        float c = (r < N_NODES) ? g_cnt[r] : 1.f;
        sInv[tid] = 1.f / fmaxf(c, 1.f);
    }
    __syncthreads();

    // A-load mapping: 64 rows x 16 k, float4 along k
    const int a_row = tid >> 2;           // 0..63
    const int a_k   = (tid & 3) * 4;      // 0,4,8,12
    // B-load mapping: 16 k-rows x 64 cols, float4 along n
    const int b_row = tid >> 4;           // 0..15
    const int b_c   = (tid & 15) * 4;     // 0..60
    // Compute mapping
    const int tx = tid & 15;              // n
    const int ty = tid >> 4;              // m

    const float inv = sInv[a_row];
    int gr = row0 + a_row;
    if (gr >= N_NODES) gr = N_NODES - 1;  // clamp: garbage rows never stored
    const float* pa1 = g_agg + (size_t)gr * D_IN;
    const float* pa2 = x     + (size_t)gr * D_IN;

    float acc[4][4];
#pragma unroll
    for (int i = 0; i < 4; i++)
#pragma unroll
        for (int j = 0; j < 4; j++) acc[i][j] = 0.f;

    for (int k0 = 0; k0 < D_IN; k0 += BK) {
        float4 va1 = *(const float4*)(pa1 + k0 + a_k);
        float4 va2 = *(const float4*)(pa2 + k0 + a_k);
        float4 vb1 = *(const float4*)(Wl + (size_t)(k0 + b_row) * D_HID + col0 + b_c);
        float4 vb2 = *(const float4*)(Wr + (size_t)(k0 + b_row) * D_HID + col0 + b_c);

        sA1[a_k + 0][a_row] = va1.x * inv;
        sA1[a_k + 1][a_row] = va1.y * inv;
        sA1[a_k + 2][a_row] = va1.z * inv;
        sA1[a_k + 3][a_row] = va1.w * inv;
        sA2[a_k + 0][a_row] = va2.x;
        sA2[a_k + 1][a_row] = va2.y;
        sA2[a_k + 2][a_row] = va2.z;
        sA2[a_k + 3][a_row] = va2.w;
        *(float4*)&sB1[b_row][b_c] = vb1;
        *(float4*)&sB2[b_row][b_c] = vb2;
        __syncthreads();

#pragma unroll
        for (int kk = 0; kk < BK; kk++) {
            float4 a1 = *(const float4*)&sA1[kk][ty * 4];
            float4 a2 = *(const float4*)&sA2[kk][ty * 4];
            float4 b1 = *(const float4*)&sB1[kk][tx * 4];
            float4 b2 = *(const float4*)&sB2[kk][tx * 4];
            float av1[4] = {a1.x, a1.y, a1.z, a1.w};
            float av2[4] = {a2.x, a2.y, a2.z, a2.w};
            float bv1[4] = {b1.x, b1.y, b1.z, b1.w};
            float bv2[4] = {b2.x, b2.y, b2.z, b2.w};
#pragma unroll
            for (int i = 0; i < 4; i++)
#pragma unroll
                for (int j = 0; j < 4; j++)
                    acc[i][j] += av1[i] * bv1[j] + av2[i] * bv2[j];
        }
        __syncthreads();
    }

    float4 bb = *(const float4*)(bias + col0 + tx * 4);
#pragma unroll
    for (int i = 0; i < 4; i++) {
        int r = row0 + ty * 4 + i;
        if (r < N_NODES) {
            float4 o;
            o.x = acc[i][0] + bb.x;
            o.y = acc[i][1] + bb.y;
            o.z = acc[i][2] + bb.z;
            o.w = acc[i][3] + bb.w;
            *(float4*)(out + (size_t)r * D_HID + col0 + tx * 4) = o;
        }
    }
}

extern "C" void kernel_launch(void* const* d_in, const int* in_sizes, int n_in,
                              void* d_out, int out_size) {
    const float* x    = (const float*)d_in[0];
    const void*  eidx = d_in[1];
    const float* Wl   = (const float*)d_in[2];
    const float* Wr   = (const float*)d_in[3];
    const float* bias = (const float*)d_in[4];
    float* out = (float*)d_out;

    detect_kernel<<<1, 32>>>((const unsigned int*)eidx);
    zero_kernel<<<512, 256>>>();

    const int scatter_blocks = (N_EDGES * 32 + 255) / 256;  // 1 warp per edge
    scatter_kernel<<<scatter_blocks, 256>>>(x, eidx);

    dim3 grid((N_NODES + BM - 1) / BM, D_HID / BN);
    gemm_kernel<<<grid, 256>>>(x, Wl, Wr, bias, out);
}

// round 4
// speedup vs baseline: 3.1474x; 3.1474x over previous
#include <cuda_runtime.h>
#include <cuda_bf16.h>
#include <cstdint>

#define N_NODES 50000
#define D_IN    256
#define D_HID   512
#define N_EDGES 800000
#define KTOT    512           // fused K = D_IN (mean) + D_IN (x)
#define M_PAD   50048         // 391 * 128

// ---------------- scratch (device globals; allocation-free) ----------------
__device__ float g_agg[(size_t)N_NODES * D_IN];
__device__ float g_cnt[N_NODES];
__device__ int   g_is64;
__device__ __nv_bfloat16 g_Ahi[(size_t)M_PAD * KTOT];
__device__ __nv_bfloat16 g_Alo[(size_t)M_PAD * KTOT];
__device__ __nv_bfloat16 g_Bhi[(size_t)KTOT * KTOT];   // [N=512][K=512]
__device__ __nv_bfloat16 g_Blo[(size_t)KTOT * KTOT];

// ---------------- helpers ----------------
__device__ __forceinline__ uint32_t smem_u32(const void* p) {
    uint32_t a;
    asm("{ .reg .u64 t; cvta.to.shared.u64 t, %1; cvt.u32.u64 %0, t; }" : "=r"(a) : "l"(p));
    return a;
}
// swizzled offset within a 128-row x 128-byte tile: row r, 16B-chunk j
__device__ __forceinline__ uint32_t sw_off(int r, int j) {
    return (uint32_t)(r * 128 + ((j ^ (r & 7)) << 4));
}
__device__ __forceinline__ void ldmatrix_x4(uint32_t* f, uint32_t addr) {
    asm volatile("ldmatrix.sync.aligned.m8n8.x4.shared.b16 {%0,%1,%2,%3}, [%4];"
        : "=r"(f[0]), "=r"(f[1]), "=r"(f[2]), "=r"(f[3]) : "r"(addr));
}
__device__ __forceinline__ void mma_bf16(float* d, const uint32_t* a, uint32_t b0, uint32_t b1) {
    asm volatile("mma.sync.aligned.m16n8k16.row.col.f32.bf16.bf16.f32 "
        "{%0,%1,%2,%3}, {%4,%5,%6,%7}, {%8,%9}, {%0,%1,%2,%3};"
        : "+f"(d[0]), "+f"(d[1]), "+f"(d[2]), "+f"(d[3])
        : "r"(a[0]), "r"(a[1]), "r"(a[2]), "r"(a[3]), "r"(b0), "r"(b1));
}

// ---------------- small kernels ----------------
__global__ void detect_kernel(const unsigned int* __restrict__ e) {
    if (threadIdx.x == 0) {
        int is64 = 1;
        for (int i = 0; i < 128; i++)
            if (e[2 * i + 1] != 0u) { is64 = 0; break; }
        g_is64 = is64;
    }
}

__global__ void zero_kernel() {
    int idx = blockIdx.x * blockDim.x + threadIdx.x;
    int stride = gridDim.x * blockDim.x;
    float4 z = make_float4(0.f, 0.f, 0.f, 0.f);
    float4* a4 = reinterpret_cast<float4*>(g_agg);
    const int n4 = N_NODES * D_IN / 4;
    for (int i = idx; i < n4; i += stride) a4[i] = z;
    for (int i = idx; i < N_NODES; i += stride) g_cnt[i] = 0.f;
}

// one warp per edge; vectorized red.global.add.v4.f32
__global__ __launch_bounds__(256) void scatter_kernel(
    const float* __restrict__ x, const void* __restrict__ eidx)
{
    int gw   = (blockIdx.x * blockDim.x + threadIdx.x) >> 5;
    int lane = threadIdx.x & 31;
    if (gw >= N_EDGES) return;

    int src, dst;
    if (g_is64) {
        const long long* p = (const long long*)eidx;
        src = (int)p[gw];
        dst = (int)p[N_EDGES + gw];
    } else {
        const int* p = (const int*)eidx;
        src = p[gw];
        dst = p[N_EDGES + gw];
    }

    const float4* xs = (const float4*)(x + (size_t)src * D_IN);
    float* ad = g_agg + (size_t)dst * D_IN;

#pragma unroll
    for (int i = 0; i < 2; i++) {
        int c = lane + 32 * i;          // float4 index 0..63
        float4 v = xs[c];
        asm volatile("red.global.add.v4.f32 [%0], {%1, %2, %3, %4};"
            :: "l"(ad + 4 * c), "f"(v.x), "f"(v.y), "f"(v.z), "f"(v.w) : "memory");
    }
    if (lane == 0) atomicAdd(&g_cnt[dst], 1.0f);
}

// A' = [mean | x] -> bf16 hi/lo split, padded to M_PAD rows
__global__ __launch_bounds__(256) void convA_kernel(const float* __restrict__ x) {
    const int total = M_PAD * (KTOT / 8);
    int i = blockIdx.x * blockDim.x + threadIdx.x;
    if (i >= total) return;
    int m = i >> 6;            // 64 groups of 8 per row
    int k = (i & 63) * 8;
    float v[8];
    if (m < N_NODES) {
        if (k < D_IN) {
            float inv = 1.f / fmaxf(g_cnt[m], 1.f);
            const float4* p = (const float4*)(g_agg + (size_t)m * D_IN + k);
            float4 a = p[0], b = p[1];
            v[0]=a.x*inv; v[1]=a.y*inv; v[2]=a.z*inv; v[3]=a.w*inv;
            v[4]=b.x*inv; v[5]=b.y*inv; v[6]=b.z*inv; v[7]=b.w*inv;
        } else {
            const float4* p = (const float4*)(x + (size_t)m * D_IN + (k - D_IN));
            float4 a = p[0], b = p[1];
            v[0]=a.x; v[1]=a.y; v[2]=a.z; v[3]=a.w;
            v[4]=b.x; v[5]=b.y; v[6]=b.z; v[7]=b.w;
        }
    } else {
#pragma unroll
        for (int j = 0; j < 8; j++) v[j] = 0.f;
    }
    union { __nv_bfloat16 h[8]; uint4 u; } hi, lo;
#pragma unroll
    for (int j = 0; j < 8; j++) {
        hi.h[j] = __float2bfloat16_rn(v[j]);
        lo.h[j] = __float2bfloat16_rn(v[j] - __bfloat162float(hi.h[j]));
    }
    ((uint4*)g_Ahi)[i] = hi.u;
    ((uint4*)g_Alo)[i] = lo.u;
}

// B'[n][k] = (k<256 ? Wl[k][n] : Wr[k-256][n]) -> bf16 hi/lo (K-major rows)
__global__ __launch_bounds__(256) void convB_kernel(
    const float* __restrict__ Wl, const float* __restrict__ Wr)
{
    int i = blockIdx.x * blockDim.x + threadIdx.x;
    if (i >= KTOT * KTOT) return;
    int n = i >> 9, k = i & 511;
    float w = (k < D_IN) ? Wl[(size_t)k * D_HID + n] : Wr[(size_t)(k - D_IN) * D_HID + n];
    __nv_bfloat16 hi = __float2bfloat16_rn(w);
    __nv_bfloat16 lo = __float2bfloat16_rn(w - __bfloat162float(hi));
    g_Bhi[i] = hi;
    g_Blo[i] = lo;
}

// ---------------- mma.sync GEMM: out = A'@B'^T + bias ----------------
// Block 128x128, KC=64 double-buffered. 8 warps, warp tile 32x64.
// 3-term bf16 split: D = Ah*Bh + Ah*Bl + Al*Bh.
#define BM 128
#define BN 128
#define KC 64
#define NCHUNK (KTOT / KC)                  // 8
#define TILE_BYTES (BM * KC * 2)            // 16384 (128 rows x 128B, SW128)
#define SMEM_TOTAL (8 * TILE_BYTES)         // 131072

__device__ __forceinline__ void load_chunk(uint32_t sb, int s, int c, int row0, int col0, int tid) {
    const __nv_bfloat16* srcs[4];
    srcs[0] = g_Ahi + (size_t)row0 * KTOT + c * KC;
    srcs[1] = g_Alo + (size_t)row0 * KTOT + c * KC;
    srcs[2] = g_Bhi + (size_t)col0 * KTOT + c * KC;
    srcs[3] = g_Blo + (size_t)col0 * KTOT + c * KC;
#pragma unroll
    for (int i = 0; i < 16; i++) {
        int lin  = i * 256 + tid;        // 0..4095, 16B granules
        int tile = lin >> 10;
        int w    = lin & 1023;
        int r    = w >> 3;               // row 0..127
        int j    = w & 7;                // 16B col within 128B row
        const char* gp = (const char*)srcs[tile] + (size_t)r * (KTOT * 2) + j * 16;
        uint32_t daddr = sb + (uint32_t)(s * 4 + tile) * TILE_BYTES + sw_off(r, j);
        asm volatile("cp.async.cg.shared.global [%0], [%1], 16;" :: "r"(daddr), "l"(gp) : "memory");
    }
    asm volatile("cp.async.commit_group;" ::: "memory");
}

__global__ __launch_bounds__(256, 1) void gemm_mma(
    const float* __restrict__ bias, float* __restrict__ out)
{
    extern __shared__ char smem[];
    uint32_t sb = smem_u32(smem);
    const int tid = threadIdx.x, wid = tid >> 5, lane = tid & 31;
    const int row0 = blockIdx.x * BM, col0 = blockIdx.y * BN;
    const int warp_m = (wid & 3) * 32;      // 0,32,64,96
    const int warp_n = (wid >> 2) * 64;     // 0,64

    float acc[2][8][4];
#pragma unroll
    for (int mi = 0; mi < 2; mi++)
#pragma unroll
        for (int ni = 0; ni < 8; ni++)
#pragma unroll
            for (int j = 0; j < 4; j++) acc[mi][ni][j] = 0.f;

    // ldmatrix per-thread row/chunk offsets
    const int lmat = lane >> 3;             // matrix 0..3
    const int lrow = lane & 7;              // row within 8x8

    load_chunk(sb, 0, 0, row0, col0, tid);

    for (int c = 0; c < NCHUNK; c++) {
        const int s = c & 1;
        if (c + 1 < NCHUNK) {
            load_chunk(sb, s ^ 1, c + 1, row0, col0, tid);
            asm volatile("cp.async.wait_group 1;" ::: "memory");
        } else {
            asm volatile("cp.async.wait_group 0;" ::: "memory");
        }
        __syncthreads();

        const uint32_t tAh = sb + (uint32_t)(s * 4 + 0) * TILE_BYTES;
        const uint32_t tAl = sb + (uint32_t)(s * 4 + 1) * TILE_BYTES;
        const uint32_t tBh = sb + (uint32_t)(s * 4 + 2) * TILE_BYTES;
        const uint32_t tBl = sb + (uint32_t)(s * 4 + 3) * TILE_BYTES;

#pragma unroll
        for (int kk = 0; kk < 4; kk++) {    // 4 k16-steps per KC=64
            // A fragments: mat layout -> {rows 0-7,k lo},{rows 8-15,k lo},{rows 0-7,k hi},{rows 8-15,k hi}
            uint32_t ah[2][4], al[2][4];
#pragma unroll
            for (int mi = 0; mi < 2; mi++) {
                int ra = warp_m + mi * 16 + (lmat & 1) * 8 + lrow;
                int ja = kk * 2 + (lmat >> 1);
                ldmatrix_x4(ah[mi], tAh + sw_off(ra, ja));
                ldmatrix_x4(al[mi], tAl + sw_off(ra, ja));
            }
            // B fragments: per pair np covers n-tiles 2np, 2np+1
            int rb = warp_n + (lmat >> 1) * 8 + lrow;   // + np*16
            int jb = kk * 2 + (lmat & 1);
#pragma unroll
            for (int np = 0; np < 4; np++) {
                uint32_t bh[4], bl[4];
                ldmatrix_x4(bh, tBh + sw_off(rb + np * 16, jb));
                ldmatrix_x4(bl, tBl + sw_off(rb + np * 16, jb));
#pragma unroll
                for (int mi = 0; mi < 2; mi++) {
#pragma unroll
                    for (int q = 0; q < 2; q++) {
                        int ni = np * 2 + q;
                        mma_bf16(acc[mi][ni], ah[mi], bh[2 * q], bh[2 * q + 1]);
                        mma_bf16(acc[mi][ni], ah[mi], bl[2 * q], bl[2 * q + 1]);
                        mma_bf16(acc[mi][ni], al[mi], bh[2 * q], bh[2 * q + 1]);
                    }
                }
            }
        }
        __syncthreads();
    }

    // epilogue: thread t holds cols n0+(t%4)*2, rows +t/4 and +8+t/4
    const int qrow = lane >> 2, qcol = (lane & 3) * 2;
#pragma unroll
    for (int mi = 0; mi < 2; mi++) {
        int r0 = row0 + warp_m + mi * 16 + qrow;
#pragma unroll
        for (int ni = 0; ni < 8; ni++) {
            int cn = col0 + warp_n + ni * 8 + qcol;
            float2 bb = *(const float2*)(bias + cn);
            if (r0 < N_NODES) {
                float2 o0 = make_float2(acc[mi][ni][0] + bb.x, acc[mi][ni][1] + bb.y);
                *(float2*)(out + (size_t)r0 * D_HID + cn) = o0;
            }
            if (r0 + 8 < N_NODES) {
                float2 o1 = make_float2(acc[mi][ni][2] + bb.x, acc[mi][ni][3] + bb.y);
                *(float2*)(out + (size_t)(r0 + 8) * D_HID + cn) = o1;
            }
        }
    }
}

// ---------------- launch ----------------
extern "C" void kernel_launch(void* const* d_in, const int* in_sizes, int n_in,
                              void* d_out, int out_size) {
    const float* x    = (const float*)d_in[0];
    const void*  eidx = d_in[1];
    const float* Wl   = (const float*)d_in[2];
    const float* Wr   = (const float*)d_in[3];
    const float* bias = (const float*)d_in[4];
    float* out = (float*)d_out;

    cudaFuncSetAttribute(gemm_mma, cudaFuncAttributeMaxDynamicSharedMemorySize, SMEM_TOTAL);

    detect_kernel<<<1, 32>>>((const unsigned int*)eidx);
    zero_kernel<<<512, 256>>>();

    const int scatter_blocks = (N_EDGES * 32 + 255) / 256;
    scatter_kernel<<<scatter_blocks, 256>>>(x, eidx);

    convA_kernel<<<(M_PAD * (KTOT / 8) + 255) / 256, 256>>>(x);
    convB_kernel<<<(KTOT * KTOT + 255) / 256, 256>>>(Wl, Wr);

    dim3 grid(M_PAD / BM, D_HID / BN);
    gemm_mma<<<grid, 256, SMEM_TOTAL>>>(bias, out);
}

// round 8
// speedup vs baseline: 3.4337x; 1.0910x over previous
#include <cuda_runtime.h>
#include <cuda_bf16.h>
#include <cstdint>

#define N_NODES 50000
#define D_IN    256
#define D_HID   512
#define N_EDGES 800000
#define KTOT    512           // fused K = D_IN (mean) + D_IN (x)
#define M_PAD   50048         // 391 * 128

// ---------------- scratch (device globals; allocation-free) ----------------
__device__ int   g_is64;
__device__ int   g_cnt_i[N_NODES];
__device__ int   g_off[N_NODES + 1];
__device__ int   g_cursor[N_NODES];
__device__ int   g_csr[N_EDGES];
__device__ __nv_bfloat16 g_Ahi[(size_t)M_PAD * KTOT];
__device__ __nv_bfloat16 g_Alo[(size_t)M_PAD * KTOT];
__device__ __nv_bfloat16 g_Bhi[(size_t)KTOT * KTOT];   // [N=512][K=512]
__device__ __nv_bfloat16 g_Blo[(size_t)KTOT * KTOT];

// ---------------- helpers ----------------
__device__ __forceinline__ uint32_t smem_u32(const void* p) {
    uint32_t a;
    asm("{ .reg .u64 t; cvta.to.shared.u64 t, %1; cvt.u32.u64 %0, t; }" : "=r"(a) : "l"(p));
    return a;
}
// swizzled offset within a 128-row x 128-byte tile: row r, 16B-chunk j
__device__ __forceinline__ uint32_t sw_off(int r, int j) {
    return (uint32_t)(r * 128 + ((j ^ (r & 7)) << 4));
}
__device__ __forceinline__ void ldmatrix_x4(uint32_t* f, uint32_t addr) {
    asm volatile("ldmatrix.sync.aligned.m8n8.x4.shared.b16 {%0,%1,%2,%3}, [%4];"
        : "=r"(f[0]), "=r"(f[1]), "=r"(f[2]), "=r"(f[3]) : "r"(addr));
}
__device__ __forceinline__ void mma_bf16(float* d, const uint32_t* a, uint32_t b0, uint32_t b1) {
    asm volatile("mma.sync.aligned.m16n8k16.row.col.f32.bf16.bf16.f32 "
        "{%0,%1,%2,%3}, {%4,%5,%6,%7}, {%8,%9}, {%0,%1,%2,%3};"
        : "+f"(d[0]), "+f"(d[1]), "+f"(d[2]), "+f"(d[3])
        : "r"(a[0]), "r"(a[1]), "r"(a[2]), "r"(a[3]), "r"(b0), "r"(b1));
}

__device__ __forceinline__ void edge_pair(const void* eidx, int e, int& src, int& dst) {
    if (g_is64) {
        const long long* p = (const long long*)eidx;
        src = (int)p[e];
        dst = (int)p[N_EDGES + e];
    } else {
        const int* p = (const int*)eidx;
        src = p[e];
        dst = p[N_EDGES + e];
    }
}

// ---------------- CSR build ----------------
__global__ void detect_kernel(const unsigned int* __restrict__ e) {
    if (threadIdx.x == 0) {
        int is64 = 1;
        for (int i = 0; i < 128; i++)
            if (e[2 * i + 1] != 0u) { is64 = 0; break; }
        g_is64 = is64;
    }
}

__global__ void zero_counts_kernel() {
    int i = blockIdx.x * blockDim.x + threadIdx.x;
    if (i < N_NODES) g_cnt_i[i] = 0;
}

__global__ __launch_bounds__(256) void hist_kernel(const void* __restrict__ eidx) {
    int e = blockIdx.x * blockDim.x + threadIdx.x;
    if (e >= N_EDGES) return;
    int src, dst;
    edge_pair(eidx, e, src, dst);
    atomicAdd(&g_cnt_i[dst], 1);
}

__global__ __launch_bounds__(1024) void prefix_kernel() {
    __shared__ int sdata[1024];
    __shared__ int carry;
    int tid = threadIdx.x;
    if (tid == 0) carry = 0;
    __syncthreads();
    for (int base = 0; base < N_NODES; base += 1024) {
        int i = base + tid;
        int v = (i < N_NODES) ? g_cnt_i[i] : 0;
        sdata[tid] = v;
        __syncthreads();
#pragma unroll
        for (int ofs = 1; ofs < 1024; ofs <<= 1) {
            int t = (tid >= ofs) ? sdata[tid - ofs] : 0;
            __syncthreads();
            sdata[tid] += t;
            __syncthreads();
        }
        int excl = sdata[tid] - v + carry;
        if (i < N_NODES) { g_off[i] = excl; g_cursor[i] = excl; }
        __syncthreads();
        if (tid == 0) carry += sdata[1023];
        __syncthreads();
    }
    if (tid == 0) g_off[N_NODES] = carry;
}

__global__ __launch_bounds__(256) void fill_kernel(const void* __restrict__ eidx) {
    int e = blockIdx.x * blockDim.x + threadIdx.x;
    if (e >= N_EDGES) return;
    int src, dst;
    edge_pair(eidx, e, src, dst);
    int pos = atomicAdd(&g_cursor[dst], 1);
    g_csr[pos] = src;
}

// ---------------- gather + bf16 split conversion (fused) ----------------
__device__ __forceinline__ void write_hilo4(__nv_bfloat16* ph, __nv_bfloat16* pl,
                                            const float* v, float s) {
    union { __nv_bfloat16 h[4]; uint2 u; } hi, lo;
#pragma unroll
    for (int j = 0; j < 4; j++) {
        float f = v[j] * s;
        hi.h[j] = __float2bfloat16_rn(f);
        lo.h[j] = __float2bfloat16_rn(f - __bfloat162float(hi.h[j]));
    }
    *(uint2*)ph = hi.u;
    *(uint2*)pl = lo.u;
}

__global__ __launch_bounds__(256) void gather_kernel(const float* __restrict__ x) {
    int node = blockIdx.x * 8 + (threadIdx.x >> 5);
    int lane = threadIdx.x & 31;
    if (node >= M_PAD) return;

    __nv_bfloat16* rh = g_Ahi + (size_t)node * KTOT;
    __nv_bfloat16* rl = g_Alo + (size_t)node * KTOT;

    if (node >= N_NODES) {     // zero padding rows
        uint4 z = make_uint4(0, 0, 0, 0);
        ((uint4*)rh)[lane] = z; ((uint4*)rh)[lane + 32] = z;
        ((uint4*)rl)[lane] = z; ((uint4*)rl)[lane + 32] = z;
        return;
    }

    const int off0 = g_off[node];
    const int deg  = g_off[node + 1] - off0;
    const float4* xb = (const float4*)x;

    float a0[4] = {0, 0, 0, 0}, a1[4] = {0, 0, 0, 0};
#pragma unroll 4
    for (int j = 0; j < deg; j++) {
        int src = g_csr[off0 + j];
        const float4* xs = xb + (size_t)src * 64;
        float4 v0 = xs[lane], v1 = xs[lane + 32];
        a0[0] += v0.x; a0[1] += v0.y; a0[2] += v0.z; a0[3] += v0.w;
        a1[0] += v1.x; a1[1] += v1.y; a1[2] += v1.z; a1[3] += v1.w;
    }
    float inv = 1.f / fmaxf((float)deg, 1.f);
    write_hilo4(rh + 4 * lane, rl + 4 * lane, a0, inv);
    write_hilo4(rh + 4 * (lane + 32), rl + 4 * (lane + 32), a1, inv);

    // x-half (cols 256..511)
    const float4* xs = xb + (size_t)node * 64;
    float4 v0 = xs[lane], v1 = xs[lane + 32];
    float b0[4] = {v0.x, v0.y, v0.z, v0.w};
    float b1[4] = {v1.x, v1.y, v1.z, v1.w};
    write_hilo4(rh + D_IN + 4 * lane, rl + D_IN + 4 * lane, b0, 1.f);
    write_hilo4(rh + D_IN + 4 * (lane + 32), rl + D_IN + 4 * (lane + 32), b1, 1.f);
}

// B'[n][k] = (k<256 ? Wl[k][n] : Wr[k-256][n]) -> bf16 hi/lo (K-major rows)
__global__ __launch_bounds__(256) void convB_kernel(
    const float* __restrict__ Wl, const float* __restrict__ Wr)
{
    int i = blockIdx.x * blockDim.x + threadIdx.x;
    if (i >= KTOT * KTOT) return;
    int n = i >> 9, k = i & 511;
    float w = (k < D_IN) ? Wl[(size_t)k * D_HID + n] : Wr[(size_t)(k - D_IN) * D_HID + n];
    __nv_bfloat16 hi = __float2bfloat16_rn(w);
    __nv_bfloat16 lo = __float2bfloat16_rn(w - __bfloat162float(hi));
    g_Bhi[i] = hi;
    g_Blo[i] = lo;
}

// ---------------- mma.sync GEMM: out = A'@B'^T + bias ----------------
#define BM 128
#define BN 128
#define KC 64
#define NCHUNK (KTOT / KC)                  // 8
#define TILE_BYTES (BM * KC * 2)            // 16384 (128 rows x 128B, SW128)
#define SMEM_TOTAL (8 * TILE_BYTES)         // 131072

__device__ __forceinline__ void load_chunk(uint32_t sb, int s, int c, int row0, int col0, int tid) {
    const __nv_bfloat16* srcs[4];
    srcs[0] = g_Ahi + (size_t)row0 * KTOT + c * KC;
    srcs[1] = g_Alo + (size_t)row0 * KTOT + c * KC;
    srcs[2] = g_Bhi + (size_t)col0 * KTOT + c * KC;
    srcs[3] = g_Blo + (size_t)col0 * KTOT + c * KC;
#pragma unroll
    for (int i = 0; i < 16; i++) {
        int lin  = i * 256 + tid;        // 0..4095, 16B granules
        int tile = lin >> 10;
        int w    = lin & 1023;
        int r    = w >> 3;               // row 0..127
        int j    = w & 7;                // 16B col within 128B row
        const char* gp = (const char*)srcs[tile] + (size_t)r * (KTOT * 2) + j * 16;
        uint32_t daddr = sb + (uint32_t)(s * 4 + tile) * TILE_BYTES + sw_off(r, j);
        asm volatile("cp.async.cg.shared.global [%0], [%1], 16;" :: "r"(daddr), "l"(gp) : "memory");
    }
    asm volatile("cp.async.commit_group;" ::: "memory");
}

__global__ __launch_bounds__(256, 1) void gemm_mma(
    const float* __restrict__ bias, float* __restrict__ out)
{
    extern __shared__ char smem[];
    uint32_t sb = smem_u32(smem);
    const int tid = threadIdx.x, wid = tid >> 5, lane = tid & 31;
    const int row0 = blockIdx.x * BM, col0 = blockIdx.y * BN;
    const int warp_m = (wid & 3) * 32;      // 0,32,64,96
    const int warp_n = (wid >> 2) * 64;     // 0,64

    float acc[2][8][4];
#pragma unroll
    for (int mi = 0; mi < 2; mi++)
#pragma unroll
        for (int ni = 0; ni < 8; ni++)
#pragma unroll
            for (int j = 0; j < 4; j++) acc[mi][ni][j] = 0.f;

    const int lmat = lane >> 3;             // matrix 0..3
    const int lrow = lane & 7;              // row within 8x8

    load_chunk(sb, 0, 0, row0, col0, tid);

    for (int c = 0; c < NCHUNK; c++) {
        const int s = c & 1;
        if (c + 1 < NCHUNK) {
            load_chunk(sb, s ^ 1, c + 1, row0, col0, tid);
            asm volatile("cp.async.wait_group 1;" ::: "memory");
        } else {
            asm volatile("cp.async.wait_group 0;" ::: "memory");
        }
        __syncthreads();

        const uint32_t tAh = sb + (uint32_t)(s * 4 + 0) * TILE_BYTES;
        const uint32_t tAl = sb + (uint32_t)(s * 4 + 1) * TILE_BYTES;
        const uint32_t tBh = sb + (uint32_t)(s * 4 + 2) * TILE_BYTES;
        const uint32_t tBl = sb + (uint32_t)(s * 4 + 3) * TILE_BYTES;

#pragma unroll
        for (int kk = 0; kk < 4; kk++) {    // 4 k16-steps per KC=64
            uint32_t ah[2][4], al[2][4];
#pragma unroll
            for (int mi = 0; mi < 2; mi++) {
                int ra = warp_m + mi * 16 + (lmat & 1) * 8 + lrow;
                int ja = kk * 2 + (lmat >> 1);
                ldmatrix_x4(ah[mi], tAh + sw_off(ra, ja));
                ldmatrix_x4(al[mi], tAl + sw_off(ra, ja));
            }
            int rb = warp_n + (lmat >> 1) * 8 + lrow;
            int jb = kk * 2 + (lmat & 1);
#pragma unroll
            for (int np = 0; np < 4; np++) {
                uint32_t bh[4], bl[4];
                ldmatrix_x4(bh, tBh + sw_off(rb + np * 16, jb));
                ldmatrix_x4(bl, tBl + sw_off(rb + np * 16, jb));
#pragma unroll
                for (int mi = 0; mi < 2; mi++) {
#pragma unroll
                    for (int q = 0; q < 2; q++) {
                        int ni = np * 2 + q;
                        mma_bf16(acc[mi][ni], ah[mi], bh[2 * q], bh[2 * q + 1]);
                        mma_bf16(acc[mi][ni], ah[mi], bl[2 * q], bl[2 * q + 1]);
                        mma_bf16(acc[mi][ni], al[mi], bh[2 * q], bh[2 * q + 1]);
                    }
                }
            }
        }
        __syncthreads();
    }

    const int qrow = lane >> 2, qcol = (lane & 3) * 2;
#pragma unroll
    for (int mi = 0; mi < 2; mi++) {
        int r0 = row0 + warp_m + mi * 16 + qrow;
#pragma unroll
        for (int ni = 0; ni < 8; ni++) {
            int cn = col0 + warp_n + ni * 8 + qcol;
            float2 bb = *(const float2*)(bias + cn);
            if (r0 < N_NODES) {
                float2 o0 = make_float2(acc[mi][ni][0] + bb.x, acc[mi][ni][1] + bb.y);
                *(float2*)(out + (size_t)r0 * D_HID + cn) = o0;
            }
            if (r0 + 8 < N_NODES) {
                float2 o1 = make_float2(acc[mi][ni][2] + bb.x, acc[mi][ni][3] + bb.y);
                *(float2*)(out + (size_t)(r0 + 8) * D_HID + cn) = o1;
            }
        }
    }
}

// ---------------- launch ----------------
extern "C" void kernel_launch(void* const* d_in, const int* in_sizes, int n_in,
                              void* d_out, int out_size) {
    const float* x    = (const float*)d_in[0];
    const void*  eidx = d_in[1];
    const float* Wl   = (const float*)d_in[2];
    const float* Wr   = (const float*)d_in[3];
    const float* bias = (const float*)d_in[4];
    float* out = (float*)d_out;

    cudaFuncSetAttribute(gemm_mma, cudaFuncAttributeMaxDynamicSharedMemorySize, SMEM_TOTAL);

    detect_kernel<<<1, 32>>>((const unsigned int*)eidx);
    zero_counts_kernel<<<(N_NODES + 255) / 256, 256>>>();
    hist_kernel<<<(N_EDGES + 255) / 256, 256>>>(eidx);
    prefix_kernel<<<1, 1024>>>();
    fill_kernel<<<(N_EDGES + 255) / 256, 256>>>(eidx);
    gather_kernel<<<(M_PAD + 7) / 8, 256>>>(x);
    convB_kernel<<<(KTOT * KTOT + 255) / 256, 256>>>(Wl, Wr);

    dim3 grid(M_PAD / BM, D_HID / BN);
    gemm_mma<<<grid, 256, SMEM_TOTAL>>>(bias, out);
}

// round 9
// speedup vs baseline: 4.1910x; 1.2206x over previous
#include <cuda_runtime.h>
#include <cuda_bf16.h>
#include <cstdint>

#define N_NODES 50000
#define D_IN    256
#define D_HID   512
#define N_EDGES 800000
#define KTOT    512           // fused K = D_IN (mean) + D_IN (x)
#define M_PAD   50048         // 391 * 128
#define SCAN_BLOCKS 49        // 49 * 1024 = 50176 >= N_NODES

// ---------------- scratch (device globals; allocation-free) ----------------
__device__ int   g_is64;
__device__ int   g_cnt_i[N_NODES];
__device__ int   g_off[N_NODES + 1];
__device__ int   g_cursor[N_NODES];
__device__ int   g_csr[N_EDGES];
__device__ int   g_bsum[64];
__device__ __nv_bfloat16 g_Ahi[(size_t)M_PAD * KTOT];
__device__ __nv_bfloat16 g_Alo[(size_t)M_PAD * KTOT];
__device__ __nv_bfloat16 g_Bhi[(size_t)KTOT * KTOT];   // [N=512][K=512]
__device__ __nv_bfloat16 g_Blo[(size_t)KTOT * KTOT];

// ---------------- helpers ----------------
__device__ __forceinline__ uint32_t smem_u32(const void* p) {
    uint32_t a;
    asm("{ .reg .u64 t; cvta.to.shared.u64 t, %1; cvt.u32.u64 %0, t; }" : "=r"(a) : "l"(p));
    return a;
}
// swizzled offset within a 128-row x 128-byte tile: row r, 16B-chunk j
__device__ __forceinline__ uint32_t sw_off(int r, int j) {
    return (uint32_t)(r * 128 + ((j ^ (r & 7)) << 4));
}
__device__ __forceinline__ void ldmatrix_x4(uint32_t* f, uint32_t addr) {
    asm volatile("ldmatrix.sync.aligned.m8n8.x4.shared.b16 {%0,%1,%2,%3}, [%4];"
        : "=r"(f[0]), "=r"(f[1]), "=r"(f[2]), "=r"(f[3]) : "r"(addr));
}
__device__ __forceinline__ void mma_bf16(float* d, const uint32_t* a, uint32_t b0, uint32_t b1) {
    asm volatile("mma.sync.aligned.m16n8k16.row.col.f32.bf16.bf16.f32 "
        "{%0,%1,%2,%3}, {%4,%5,%6,%7}, {%8,%9}, {%0,%1,%2,%3};"
        : "+f"(d[0]), "+f"(d[1]), "+f"(d[2]), "+f"(d[3])
        : "r"(a[0]), "r"(a[1]), "r"(a[2]), "r"(a[3]), "r"(b0), "r"(b1));
}

__device__ __forceinline__ void edge_pair(const void* eidx, int e, int& src, int& dst) {
    if (g_is64) {
        const long long* p = (const long long*)eidx;
        src = (int)p[e];
        dst = (int)p[N_EDGES + e];
    } else {
        const int* p = (const int*)eidx;
        src = p[e];
        dst = p[N_EDGES + e];
    }
}

// ---------------- CSR build ----------------
__global__ void detect_kernel(const unsigned int* __restrict__ e) {
    if (threadIdx.x == 0) {
        int is64 = 1;
        for (int i = 0; i < 128; i++)
            if (e[2 * i + 1] != 0u) { is64 = 0; break; }
        g_is64 = is64;
    }
}

__global__ void zero_counts_kernel() {
    int i = blockIdx.x * blockDim.x + threadIdx.x;
    if (i < N_NODES) g_cnt_i[i] = 0;
}

__global__ __launch_bounds__(256) void hist_kernel(const void* __restrict__ eidx) {
    int e = blockIdx.x * blockDim.x + threadIdx.x;
    if (e >= N_EDGES) return;
    int src, dst;
    edge_pair(eidx, e, src, dst);
    atomicAdd(&g_cnt_i[dst], 1);
}

// pass 1: per-block scan (1024 elems/block), local exclusive prefix + block sum
__global__ __launch_bounds__(1024) void scan1_kernel() {
    __shared__ int sdata[1024];
    int tid = threadIdx.x;
    int i = blockIdx.x * 1024 + tid;
    int v = (i < N_NODES) ? g_cnt_i[i] : 0;
    sdata[tid] = v;
    __syncthreads();
#pragma unroll
    for (int ofs = 1; ofs < 1024; ofs <<= 1) {
        int t = (tid >= ofs) ? sdata[tid - ofs] : 0;
        __syncthreads();
        sdata[tid] += t;
        __syncthreads();
    }
    if (i < N_NODES) g_off[i] = sdata[tid] - v;      // local exclusive
    if (tid == 1023) g_bsum[blockIdx.x] = sdata[1023];
}

// pass 2: exclusive scan of SCAN_BLOCKS block sums (single warp)
__global__ void scan2_kernel() {
    int lane = threadIdx.x;
    int v0 = (lane < SCAN_BLOCKS) ? g_bsum[lane] : 0;        // 0..31
    int v1 = (32 + lane < SCAN_BLOCKS) ? g_bsum[32 + lane] : 0;
    int s0 = v0, s1 = v1;
#pragma unroll
    for (int ofs = 1; ofs < 32; ofs <<= 1) {
        int t0 = __shfl_up_sync(0xffffffffu, s0, ofs);
        int t1 = __shfl_up_sync(0xffffffffu, s1, ofs);
        if (lane >= ofs) { s0 += t0; s1 += t1; }
    }
    int tot0 = __shfl_sync(0xffffffffu, s0, 31);             // sum of first 32
    if (lane < SCAN_BLOCKS) g_bsum[lane] = s0 - v0;
    if (32 + lane < SCAN_BLOCKS) g_bsum[32 + lane] = tot0 + s1 - v1;
    int tot1 = __shfl_sync(0xffffffffu, s1, 31);
    if (lane == 0) g_off[N_NODES] = tot0 + tot1;             // == N_EDGES
}

// pass 3: add block offsets, write cursor
__global__ __launch_bounds__(1024) void scan3_kernel() {
    int i = blockIdx.x * 1024 + threadIdx.x;
    if (i >= N_NODES) return;
    int v = g_off[i] + g_bsum[blockIdx.x];
    g_off[i] = v;
    g_cursor[i] = v;
}

__global__ __launch_bounds__(256) void fill_kernel(const void* __restrict__ eidx) {
    int e = blockIdx.x * blockDim.x + threadIdx.x;
    if (e >= N_EDGES) return;
    int src, dst;
    edge_pair(eidx, e, src, dst);
    int pos = atomicAdd(&g_cursor[dst], 1);
    g_csr[pos] = src;
}

// ---------------- gather + bf16 split conversion (fused) ----------------
__device__ __forceinline__ void write_hilo4(__nv_bfloat16* ph, __nv_bfloat16* pl,
                                            const float* v, float s) {
    union { __nv_bfloat16 h[4]; uint2 u; } hi, lo;
#pragma unroll
    for (int j = 0; j < 4; j++) {
        float f = v[j] * s;
        hi.h[j] = __float2bfloat16_rn(f);
        lo.h[j] = __float2bfloat16_rn(f - __bfloat162float(hi.h[j]));
    }
    *(uint2*)ph = hi.u;
    *(uint2*)pl = lo.u;
}

__global__ __launch_bounds__(256) void gather_kernel(const float* __restrict__ x) {
    int node = blockIdx.x * 8 + (threadIdx.x >> 5);
    int lane = threadIdx.x & 31;
    if (node >= M_PAD) return;

    __nv_bfloat16* rh = g_Ahi + (size_t)node * KTOT;
    __nv_bfloat16* rl = g_Alo + (size_t)node * KTOT;

    if (node >= N_NODES) {     // zero padding rows
        uint4 z = make_uint4(0, 0, 0, 0);
        ((uint4*)rh)[lane] = z; ((uint4*)rh)[lane + 32] = z;
        ((uint4*)rl)[lane] = z; ((uint4*)rl)[lane + 32] = z;
        return;
    }

    const int off0 = g_off[node];
    const int deg  = g_off[node + 1] - off0;
    const float4* xb = (const float4*)x;

    float a0[4] = {0, 0, 0, 0}, a1[4] = {0, 0, 0, 0};
#pragma unroll 4
    for (int j = 0; j < deg; j++) {
        int src = g_csr[off0 + j];
        const float4* xs = xb + (size_t)src * 64;
        float4 v0 = xs[lane], v1 = xs[lane + 32];
        a0[0] += v0.x; a0[1] += v0.y; a0[2] += v0.z; a0[3] += v0.w;
        a1[0] += v1.x; a1[1] += v1.y; a1[2] += v1.z; a1[3] += v1.w;
    }
    float inv = 1.f / fmaxf((float)deg, 1.f);
    write_hilo4(rh + 4 * lane, rl + 4 * lane, a0, inv);
    write_hilo4(rh + 4 * (lane + 32), rl + 4 * (lane + 32), a1, inv);

    // x-half (cols 256..511)
    const float4* xs = xb + (size_t)node * 64;
    float4 v0 = xs[lane], v1 = xs[lane + 32];
    float b0[4] = {v0.x, v0.y, v0.z, v0.w};
    float b1[4] = {v1.x, v1.y, v1.z, v1.w};
    write_hilo4(rh + D_IN + 4 * lane, rl + D_IN + 4 * lane, b0, 1.f);
    write_hilo4(rh + D_IN + 4 * (lane + 32), rl + D_IN + 4 * (lane + 32), b1, 1.f);
}

// B'[n][k] = (k<256 ? Wl[k][n] : Wr[k-256][n]) -> bf16 hi/lo (K-major rows)
__global__ __launch_bounds__(256) void convB_kernel(
    const float* __restrict__ Wl, const float* __restrict__ Wr)
{
    int i = blockIdx.x * blockDim.x + threadIdx.x;
    if (i >= KTOT * KTOT) return;
    int n = i >> 9, k = i & 511;
    float w = (k < D_IN) ? Wl[(size_t)k * D_HID + n] : Wr[(size_t)(k - D_IN) * D_HID + n];
    __nv_bfloat16 hi = __float2bfloat16_rn(w);
    __nv_bfloat16 lo = __float2bfloat16_rn(w - __bfloat162float(hi));
    g_Bhi[i] = hi;
    g_Blo[i] = lo;
}

// ---------------- mma.sync GEMM: out = A'@B'^T + bias ----------------
#define BM 128
#define BN 128
#define KC 64
#define NCHUNK (KTOT / KC)                  // 8
#define TILE_BYTES (BM * KC * 2)            // 16384 (128 rows x 128B, SW128)
#define SMEM_TOTAL (8 * TILE_BYTES)         // 131072

__device__ __forceinline__ void load_chunk(uint32_t sb, int s, int c, int row0, int col0, int tid) {
    const __nv_bfloat16* srcs[4];
    srcs[0] = g_Ahi + (size_t)row0 * KTOT + c * KC;
    srcs[1] = g_Alo + (size_t)row0 * KTOT + c * KC;
    srcs[2] = g_Bhi + (size_t)col0 * KTOT + c * KC;
    srcs[3] = g_Blo + (size_t)col0 * KTOT + c * KC;
#pragma unroll
    for (int i = 0; i < 16; i++) {
        int lin  = i * 256 + tid;        // 0..4095, 16B granules
        int tile = lin >> 10;
        int w    = lin & 1023;
        int r    = w >> 3;               // row 0..127
        int j    = w & 7;                // 16B col within 128B row
        const char* gp = (const char*)srcs[tile] + (size_t)r * (KTOT * 2) + j * 16;
        uint32_t daddr = sb + (uint32_t)(s * 4 + tile) * TILE_BYTES + sw_off(r, j);
        asm volatile("cp.async.cg.shared.global [%0], [%1], 16;" :: "r"(daddr), "l"(gp) : "memory");
    }
    asm volatile("cp.async.commit_group;" ::: "memory");
}

__global__ __launch_bounds__(256, 1) void gemm_mma(
    const float* __restrict__ bias, float* __restrict__ out)
{
    extern __shared__ char smem[];
    uint32_t sb = smem_u32(smem);
    const int tid = threadIdx.x, wid = tid >> 5, lane = tid & 31;
    const int row0 = blockIdx.x * BM, col0 = blockIdx.y * BN;
    const int warp_m = (wid & 3) * 32;      // 0,32,64,96
    const int warp_n = (wid >> 2) * 64;     // 0,64

    float acc[2][8][4];
#pragma unroll
    for (int mi = 0; mi < 2; mi++)
#pragma unroll
        for (int ni = 0; ni < 8; ni++)
#pragma unroll
            for (int j = 0; j < 4; j++) acc[mi][ni][j] = 0.f;

    const int lmat = lane >> 3;             // matrix 0..3
    const int lrow = lane & 7;              // row within 8x8

    load_chunk(sb, 0, 0, row0, col0, tid);

    for (int c = 0; c < NCHUNK; c++) {
        const int s = c & 1;
        if (c + 1 < NCHUNK) {
            load_chunk(sb, s ^ 1, c + 1, row0, col0, tid);
            asm volatile("cp.async.wait_group 1;" ::: "memory");
        } else {
            asm volatile("cp.async.wait_group 0;" ::: "memory");
        }
        __syncthreads();

        const uint32_t tAh = sb + (uint32_t)(s * 4 + 0) * TILE_BYTES;
        const uint32_t tAl = sb + (uint32_t)(s * 4 + 1) * TILE_BYTES;
        const uint32_t tBh = sb + (uint32_t)(s * 4 + 2) * TILE_BYTES;
        const uint32_t tBl = sb + (uint32_t)(s * 4 + 3) * TILE_BYTES;

#pragma unroll
        for (int kk = 0; kk < 4; kk++) {    // 4 k16-steps per KC=64
            uint32_t ah[2][4], al[2][4];
#pragma unroll
            for (int mi = 0; mi < 2; mi++) {
                int ra = warp_m + mi * 16 + (lmat & 1) * 8 + lrow;
                int ja = kk * 2 + (lmat >> 1);
                ldmatrix_x4(ah[mi], tAh + sw_off(ra, ja));
                ldmatrix_x4(al[mi], tAl + sw_off(ra, ja));
            }
            int rb = warp_n + (lmat >> 1) * 8 + lrow;
            int jb = kk * 2 + (lmat & 1);
#pragma unroll
            for (int np = 0; np < 4; np++) {
                uint32_t bh[4], bl[4];
                ldmatrix_x4(bh, tBh + sw_off(rb + np * 16, jb));
                ldmatrix_x4(bl, tBl + sw_off(rb + np * 16, jb));
#pragma unroll
                for (int mi = 0; mi < 2; mi++) {
#pragma unroll
                    for (int q = 0; q < 2; q++) {
                        int ni = np * 2 + q;
                        mma_bf16(acc[mi][ni], ah[mi], bh[2 * q], bh[2 * q + 1]);
                        mma_bf16(acc[mi][ni], ah[mi], bl[2 * q], bl[2 * q + 1]);
                        mma_bf16(acc[mi][ni], al[mi], bh[2 * q], bh[2 * q + 1]);
                    }
                }
            }
        }
        __syncthreads();
    }

    const int qrow = lane >> 2, qcol = (lane & 3) * 2;
#pragma unroll
    for (int mi = 0; mi < 2; mi++) {
        int r0 = row0 + warp_m + mi * 16 + qrow;
#pragma unroll
        for (int ni = 0; ni < 8; ni++) {
            int cn = col0 + warp_n + ni * 8 + qcol;
            float2 bb = *(const float2*)(bias + cn);
            if (r0 < N_NODES) {
                float2 o0 = make_float2(acc[mi][ni][0] + bb.x, acc[mi][ni][1] + bb.y);
                *(float2*)(out + (size_t)r0 * D_HID + cn) = o0;
            }
            if (r0 + 8 < N_NODES) {
                float2 o1 = make_float2(acc[mi][ni][2] + bb.x, acc[mi][ni][3] + bb.y);
                *(float2*)(out + (size_t)(r0 + 8) * D_HID + cn) = o1;
            }
        }
    }
}

// ---------------- launch ----------------
extern "C" void kernel_launch(void* const* d_in, const int* in_sizes, int n_in,
                              void* d_out, int out_size) {
    const float* x    = (const float*)d_in[0];
    const void*  eidx = d_in[1];
    const float* Wl   = (const float*)d_in[2];
    const float* Wr   = (const float*)d_in[3];
    const float* bias = (const float*)d_in[4];
    float* out = (float*)d_out;

    cudaFuncSetAttribute(gemm_mma, cudaFuncAttributeMaxDynamicSharedMemorySize, SMEM_TOTAL);

    detect_kernel<<<1, 32>>>((const unsigned int*)eidx);
    zero_counts_kernel<<<(N_NODES + 255) / 256, 256>>>();
    hist_kernel<<<(N_EDGES + 255) / 256, 256>>>(eidx);
    scan1_kernel<<<SCAN_BLOCKS, 1024>>>();
    scan2_kernel<<<1, 32>>>();
    scan3_kernel<<<SCAN_BLOCKS, 1024>>>();
    fill_kernel<<<(N_EDGES + 255) / 256, 256>>>(eidx);
    gather_kernel<<<(M_PAD + 7) / 8, 256>>>(x);
    convB_kernel<<<(KTOT * KTOT + 255) / 256, 256>>>(Wl, Wr);

    dim3 grid(M_PAD / BM, D_HID / BN);
    gemm_mma<<<grid, 256, SMEM_TOTAL>>>(bias, out);
}

// round 10
// speedup vs baseline: 4.2115x; 1.0049x over previous
#include <cuda_runtime.h>
#include <cuda_bf16.h>
#include <cstdint>

#define N_NODES 50000
#define D_IN    256
#define D_HID   512
#define N_EDGES 800000
#define KTOT    512           // fused K = D_IN (mean) + D_IN (x)
#define M_PAD   50048         // 391 * 128
#define SCAN_BLOCKS 49        // 49 * 1024 = 50176 >= N_NODES
#define GATHER_BLOCKS (M_PAD / 8)   // 6256
#define CONVB_BLOCKS 512            // 512 * 256 * 2 = 262144 elems

// ---------------- scratch (device globals; allocation-free) ----------------
__device__ int   g_cnt_i[N_NODES];
__device__ int   g_off[N_NODES + 1];
__device__ int   g_cursor[N_NODES];
__device__ int   g_csr[N_EDGES];
__device__ unsigned long long g_pub[SCAN_BLOCKS];
__device__ __nv_bfloat16 g_Ahi[(size_t)M_PAD * KTOT];
__device__ __nv_bfloat16 g_Alo[(size_t)M_PAD * KTOT];
__device__ __nv_bfloat16 g_Bhi[(size_t)KTOT * KTOT];   // [N=512][K=512]
__device__ __nv_bfloat16 g_Blo[(size_t)KTOT * KTOT];

// ---------------- helpers ----------------
__device__ __forceinline__ uint32_t smem_u32(const void* p) {
    uint32_t a;
    asm("{ .reg .u64 t; cvta.to.shared.u64 t, %1; cvt.u32.u64 %0, t; }" : "=r"(a) : "l"(p));
    return a;
}
// swizzled offset within a 128-row x 128-byte tile: row r, 16B-chunk j
__device__ __forceinline__ uint32_t sw_off(int r, int j) {
    return (uint32_t)(r * 128 + ((j ^ (r & 7)) << 4));
}
__device__ __forceinline__ void ldmatrix_x4(uint32_t* f, uint32_t addr) {
    asm volatile("ldmatrix.sync.aligned.m8n8.x4.shared.b16 {%0,%1,%2,%3}, [%4];"
        : "=r"(f[0]), "=r"(f[1]), "=r"(f[2]), "=r"(f[3]) : "r"(addr));
}
__device__ __forceinline__ void mma_bf16(float* d, const uint32_t* a, uint32_t b0, uint32_t b1) {
    asm volatile("mma.sync.aligned.m16n8k16.row.col.f32.bf16.bf16.f32 "
        "{%0,%1,%2,%3}, {%4,%5,%6,%7}, {%8,%9}, {%0,%1,%2,%3};"
        : "+f"(d[0]), "+f"(d[1]), "+f"(d[2]), "+f"(d[3])
        : "r"(a[0]), "r"(a[1]), "r"(a[2]), "r"(a[3]), "r"(b0), "r"(b1));
}

// per-warp dtype detection: int64 edge_index has zero hi-words.
// Must be called with all 32 lanes active.
__device__ __forceinline__ int detect_is64(const unsigned int* __restrict__ e) {
    int lane = threadIdx.x & 31;
    unsigned w = (lane < 8) ? e[2 * lane + 1] : 0u;
    unsigned m = __ballot_sync(0xffffffffu, w != 0u);
    return (m & 0xFFu) == 0u;
}

// ---------------- CSR build ----------------
__global__ void zero_kernel() {
    int i = blockIdx.x * blockDim.x + threadIdx.x;
    if (i < N_NODES) g_cnt_i[i] = 0;
    if (i < SCAN_BLOCKS) g_pub[i] = 0ull;
}

__global__ __launch_bounds__(256) void hist_kernel(const void* __restrict__ eidx) {
    int is64 = detect_is64((const unsigned int*)eidx);
    int e = blockIdx.x * blockDim.x + threadIdx.x;
    if (e >= N_EDGES) return;
    int dst = is64 ? (int)((const long long*)eidx)[N_EDGES + e]
                   : ((const int*)eidx)[N_EDGES + e];
    atomicAdd(&g_cnt_i[dst], 1);
}

// single-pass scan with decoupled aggregate lookback.
// All SCAN_BLOCKS (49 < 148 SMs) are co-resident in wave 1.
__global__ __launch_bounds__(1024) void scan_kernel() {
    __shared__ int sdata[1024];
    __shared__ int s_prefix;
    const int tid = threadIdx.x, b = blockIdx.x;
    const int i = b * 1024 + tid;
    int v = (i < N_NODES) ? g_cnt_i[i] : 0;
    sdata[tid] = v;
    __syncthreads();
#pragma unroll
    for (int ofs = 1; ofs < 1024; ofs <<= 1) {
        int t = (tid >= ofs) ? sdata[tid - ofs] : 0;
        __syncthreads();
        sdata[tid] += t;
        __syncthreads();
    }
    const int incl = sdata[tid];
    const int agg  = sdata[1023];

    if (tid == 0) {
        s_prefix = 0;
        __threadfence();
        atomicExch(&g_pub[b], ((unsigned long long)(unsigned)agg << 1) | 1ull);
    }
    __syncthreads();
    if (tid < b) {            // parallel lookback: one predecessor per thread
        unsigned long long p;
        do { p = atomicAdd(&g_pub[tid], 0ull); } while (!(p & 1ull));
        atomicAdd(&s_prefix, (int)(p >> 1));
    }
    __syncthreads();
    const int pre = s_prefix;
    if (i < N_NODES) {
        int ex = pre + incl - v;
        g_off[i] = ex;
        g_cursor[i] = ex;
    }
    if (b == SCAN_BLOCKS - 1 && tid == 1023) g_off[N_NODES] = pre + incl;
}

__global__ __launch_bounds__(256) void fill_kernel(const void* __restrict__ eidx) {
    int is64 = detect_is64((const unsigned int*)eidx);
    int e = blockIdx.x * blockDim.x + threadIdx.x;
    if (e >= N_EDGES) return;
    int src, dst;
    if (is64) {
        const long long* p = (const long long*)eidx;
        src = (int)p[e];
        dst = (int)p[N_EDGES + e];
    } else {
        const int* p = (const int*)eidx;
        src = p[e];
        dst = p[N_EDGES + e];
    }
    int pos = atomicAdd(&g_cursor[dst], 1);
    g_csr[pos] = src;
}

// ---------------- bf16 hi/lo split helper ----------------
__device__ __forceinline__ void write_hilo4(__nv_bfloat16* ph, __nv_bfloat16* pl,
                                            const float* v, float s) {
    union { __nv_bfloat16 h[4]; uint2 u; } hi, lo;
#pragma unroll
    for (int j = 0; j < 4; j++) {
        float f = v[j] * s;
        hi.h[j] = __float2bfloat16_rn(f);
        lo.h[j] = __float2bfloat16_rn(f - __bfloat162float(hi.h[j]));
    }
    *(uint2*)ph = hi.u;
    *(uint2*)pl = lo.u;
}

// ---------------- gather (agg half, cols 0..255) ----------------
__global__ __launch_bounds__(256) void gather_kernel(const float* __restrict__ x) {
    int node = blockIdx.x * 8 + (threadIdx.x >> 5);
    int lane = threadIdx.x & 31;

    __nv_bfloat16* rh = g_Ahi + (size_t)node * KTOT;
    __nv_bfloat16* rl = g_Alo + (size_t)node * KTOT;

    if (node >= N_NODES) {     // zero padding rows (cols 0..255)
        uint4 z = make_uint4(0, 0, 0, 0);
        ((uint4*)rh)[lane] = z;
        ((uint4*)rl)[lane] = z;
        return;
    }

    const int off0 = g_off[node];
    const int deg  = g_off[node + 1] - off0;
    const float4* xb = (const float4*)x;

    float a0[4] = {0, 0, 0, 0}, a1[4] = {0, 0, 0, 0};
#pragma unroll 4
    for (int j = 0; j < deg; j++) {
        int src = g_csr[off0 + j];
        const float4* xs = xb + (size_t)src * 64;
        float4 v0 = xs[lane], v1 = xs[lane + 32];
        a0[0] += v0.x; a0[1] += v0.y; a0[2] += v0.z; a0[3] += v0.w;
        a1[0] += v1.x; a1[1] += v1.y; a1[2] += v1.z; a1[3] += v1.w;
    }
    float inv = 1.f / fmaxf((float)deg, 1.f);
    write_hilo4(rh + 4 * lane, rl + 4 * lane, a0, inv);
    write_hilo4(rh + 4 * (lane + 32), rl + 4 * (lane + 32), a1, inv);
}

// ---------------- x-half conversion + convB (runs on stream 2) ----------------
__global__ __launch_bounds__(256) void xbconv_kernel(
    const float* __restrict__ x, const float* __restrict__ Wl,
    const float* __restrict__ Wr)
{
    int blk = blockIdx.x;
    if (blk < GATHER_BLOCKS) {
        // x-half: A' cols 256..511
        int node = blk * 8 + (threadIdx.x >> 5);
        int lane = threadIdx.x & 31;
        __nv_bfloat16* rh = g_Ahi + (size_t)node * KTOT + D_IN;
        __nv_bfloat16* rl = g_Alo + (size_t)node * KTOT + D_IN;
        if (node >= N_NODES) {
            uint4 z = make_uint4(0, 0, 0, 0);
            ((uint4*)rh)[lane] = z;
            ((uint4*)rl)[lane] = z;
            return;
        }
        const float4* xs = (const float4*)x + (size_t)node * 64;
        float4 v0 = xs[lane], v1 = xs[lane + 32];
        float b0[4] = {v0.x, v0.y, v0.z, v0.w};
        float b1[4] = {v1.x, v1.y, v1.z, v1.w};
        write_hilo4(rh + 4 * lane, rl + 4 * lane, b0, 1.f);
        write_hilo4(rh + 4 * (lane + 32), rl + 4 * (lane + 32), b1, 1.f);
    } else {
        // convB: B'[n][k] = (k<256 ? Wl[k][n] : Wr[k-256][n])
        int i0 = (blk - GATHER_BLOCKS) * 512 + threadIdx.x * 2;
#pragma unroll
        for (int t = 0; t < 2; t++) {
            int i = i0 + t;
            int n = i >> 9, k = i & 511;
            float w = (k < D_IN) ? Wl[(size_t)k * D_HID + n]
                                 : Wr[(size_t)(k - D_IN) * D_HID + n];
            __nv_bfloat16 hi = __float2bfloat16_rn(w);
            __nv_bfloat16 lo = __float2bfloat16_rn(w - __bfloat162float(hi));
            g_Bhi[i] = hi;
            g_Blo[i] = lo;
        }
    }
}

// ---------------- mma.sync GEMM: out = A'@B'^T + bias ----------------
#define BM 128
#define BN 128
#define KC 64
#define NCHUNK (KTOT / KC)                  // 8
#define TILE_BYTES (BM * KC * 2)            // 16384 (128 rows x 128B, SW128)
#define SMEM_TOTAL (8 * TILE_BYTES)         // 131072

__device__ __forceinline__ void load_chunk(uint32_t sb, int s, int c, int row0, int col0, int tid) {
    const __nv_bfloat16* srcs[4];
    srcs[0] = g_Ahi + (size_t)row0 * KTOT + c * KC;
    srcs[1] = g_Alo + (size_t)row0 * KTOT + c * KC;
    srcs[2] = g_Bhi + (size_t)col0 * KTOT + c * KC;
    srcs[3] = g_Blo + (size_t)col0 * KTOT + c * KC;
#pragma unroll
    for (int i = 0; i < 16; i++) {
        int lin  = i * 256 + tid;        // 0..4095, 16B granules
        int tile = lin >> 10;
        int w    = lin & 1023;
        int r    = w >> 3;               // row 0..127
        int j    = w & 7;                // 16B col within 128B row
        const char* gp = (const char*)srcs[tile] + (size_t)r * (KTOT * 2) + j * 16;
        uint32_t daddr = sb + (uint32_t)(s * 4 + tile) * TILE_BYTES + sw_off(r, j);
        asm volatile("cp.async.cg.shared.global [%0], [%1], 16;" :: "r"(daddr), "l"(gp) : "memory");
    }
    asm volatile("cp.async.commit_group;" ::: "memory");
}

__global__ __launch_bounds__(256, 1) void gemm_mma(
    const float* __restrict__ bias, float* __restrict__ out)
{
    extern __shared__ char smem[];
    uint32_t sb = smem_u32(smem);
    const int tid = threadIdx.x, wid = tid >> 5, lane = tid & 31;
    const int row0 = blockIdx.x * BM, col0 = blockIdx.y * BN;
    const int warp_m = (wid & 3) * 32;      // 0,32,64,96
    const int warp_n = (wid >> 2) * 64;     // 0,64

    float acc[2][8][4];
#pragma unroll
    for (int mi = 0; mi < 2; mi++)
#pragma unroll
        for (int ni = 0; ni < 8; ni++)
#pragma unroll
            for (int j = 0; j < 4; j++) acc[mi][ni][j] = 0.f;

    const int lmat = lane >> 3;             // matrix 0..3
    const int lrow = lane & 7;              // row within 8x8

    load_chunk(sb, 0, 0, row0, col0, tid);

    for (int c = 0; c < NCHUNK; c++) {
        const int s = c & 1;
        if (c + 1 < NCHUNK) {
            load_chunk(sb, s ^ 1, c + 1, row0, col0, tid);
            asm volatile("cp.async.wait_group 1;" ::: "memory");
        } else {
            asm volatile("cp.async.wait_group 0;" ::: "memory");
        }
        __syncthreads();

        const uint32_t tAh = sb + (uint32_t)(s * 4 + 0) * TILE_BYTES;
        const uint32_t tAl = sb + (uint32_t)(s * 4 + 1) * TILE_BYTES;
        const uint32_t tBh = sb + (uint32_t)(s * 4 + 2) * TILE_BYTES;
        const uint32_t tBl = sb + (uint32_t)(s * 4 + 3) * TILE_BYTES;

#pragma unroll
        for (int kk = 0; kk < 4; kk++) {    // 4 k16-steps per KC=64
            uint32_t ah[2][4], al[2][4];
#pragma unroll
            for (int mi = 0; mi < 2; mi++) {
                int ra = warp_m + mi * 16 + (lmat & 1) * 8 + lrow;
                int ja = kk * 2 + (lmat >> 1);
                ldmatrix_x4(ah[mi], tAh + sw_off(ra, ja));
                ldmatrix_x4(al[mi], tAl + sw_off(ra, ja));
            }
            int rb = warp_n + (lmat >> 1) * 8 + lrow;
            int jb = kk * 2 + (lmat & 1);
#pragma unroll
            for (int np = 0; np < 4; np++) {
                uint32_t bh[4], bl[4];
                ldmatrix_x4(bh, tBh + sw_off(rb + np * 16, jb));
                ldmatrix_x4(bl, tBl + sw_off(rb + np * 16, jb));
#pragma unroll
                for (int mi = 0; mi < 2; mi++) {
#pragma unroll
                    for (int q = 0; q < 2; q++) {
                        int ni = np * 2 + q;
                        mma_bf16(acc[mi][ni], ah[mi], bh[2 * q], bh[2 * q + 1]);
                        mma_bf16(acc[mi][ni], ah[mi], bl[2 * q], bl[2 * q + 1]);
                        mma_bf16(acc[mi][ni], al[mi], bh[2 * q], bh[2 * q + 1]);
                    }
                }
            }
        }
        __syncthreads();
    }

    const int qrow = lane >> 2, qcol = (lane & 3) * 2;
#pragma unroll
    for (int mi = 0; mi < 2; mi++) {
        int r0 = row0 + warp_m + mi * 16 + qrow;
#pragma unroll
        for (int ni = 0; ni < 8; ni++) {
            int cn = col0 + warp_n + ni * 8 + qcol;
            float2 bb = *(const float2*)(bias + cn);
            if (r0 < N_NODES) {
                float2 o0 = make_float2(acc[mi][ni][0] + bb.x, acc[mi][ni][1] + bb.y);
                *(float2*)(out + (size_t)r0 * D_HID + cn) = o0;
            }
            if (r0 + 8 < N_NODES) {
                float2 o1 = make_float2(acc[mi][ni][2] + bb.x, acc[mi][ni][3] + bb.y);
                *(float2*)(out + (size_t)(r0 + 8) * D_HID + cn) = o1;
            }
        }
    }
}

// ---------------- launch ----------------
extern "C" void kernel_launch(void* const* d_in, const int* in_sizes, int n_in,
                              void* d_out, int out_size) {
    const float* x    = (const float*)d_in[0];
    const void*  eidx = d_in[1];
    const float* Wl   = (const float*)d_in[2];
    const float* Wr   = (const float*)d_in[3];
    const float* bias = (const float*)d_in[4];
    float* out = (float*)d_out;

    // Host-side resources created once (host code runs only on capture /
    // correctness calls, never during graph replay).
    static cudaStream_t s2 = nullptr;
    static cudaEvent_t  evf = nullptr, evj = nullptr;
    if (s2 == nullptr) {
        cudaStreamCreateWithFlags(&s2, cudaStreamNonBlocking);
        cudaEventCreateWithFlags(&evf, cudaEventDisableTiming);
        cudaEventCreateWithFlags(&evj, cudaEventDisableTiming);
        cudaFuncSetAttribute(gemm_mma, cudaFuncAttributeMaxDynamicSharedMemorySize, SMEM_TOTAL);
    }

    // fork: x-half conversion + convB run concurrently with CSR build
    cudaEventRecord(evf, 0);
    cudaStreamWaitEvent(s2, evf, 0);
    xbconv_kernel<<<GATHER_BLOCKS + CONVB_BLOCKS, 256, 0, s2>>>(x, Wl, Wr);
    cudaEventRecord(evj, s2);

    // CSR chain on main stream
    zero_kernel<<<(N_NODES + 255) / 256, 256>>>();
    hist_kernel<<<(N_EDGES + 255) / 256, 256>>>(eidx);
    scan_kernel<<<SCAN_BLOCKS, 1024>>>();
    fill_kernel<<<(N_EDGES + 255) / 256, 256>>>(eidx);
    gather_kernel<<<GATHER_BLOCKS, 256>>>(x);

    // join, then GEMM
    cudaStreamWaitEvent(0, evj, 0);
    dim3 grid(M_PAD / BM, D_HID / BN);
    gemm_mma<<<grid, 256, SMEM_TOTAL>>>(bias, out);
}